// round 1
// baseline (speedup 1.0000x reference)
#include <cuda_runtime.h>
#include <cstdint>

#define B_    4
#define C_    256
#define H_    128
#define W_    128
#define HW_   (H_*W_)
#define COMP_ 64
#define KK_   25
#define HO_   64
#define WO_   64

// Scratch (device globals; no allocation allowed)
__device__ float g_comp[B_*COMP_*HW_];   // compressed: 4*64*128*128
__device__ float g_mask[B_*KK_*HO_*WO_]; // raw conv2 logits

// ---------------- packed f32x2 helpers ----------------
__device__ __forceinline__ unsigned long long pack2(float lo, float hi) {
    unsigned long long r;
    asm("mov.b64 %0, {%1, %2};" : "=l"(r)
        : "r"(__float_as_uint(lo)), "r"(__float_as_uint(hi)));
    return r;
}
__device__ __forceinline__ void fma2(unsigned long long& d,
                                     unsigned long long a, unsigned long long b) {
    asm("fma.rn.f32x2 %0, %1, %2, %0;" : "+l"(d) : "l"(a), "l"(b));
}
__device__ __forceinline__ float2 unpack2(unsigned long long v) {
    unsigned lo, hi;
    asm("mov.b64 {%0, %1}, %2;" : "=r"(lo), "=r"(hi) : "l"(v));
    return make_float2(__uint_as_float(lo), __uint_as_float(hi));
}

// ---------------- Kernel A: 1x1 conv (GEMM M=64, N=16384/batch, K=256) ----------------
// grid (256, 4), block 256. Dynamic smem: Wt[256*68] + Xs[32*64] floats = 77824 B.
#define WT_PAD 68
#define A_SMEM_BYTES ((C_*WT_PAD + 32*64) * 4)

__global__ __launch_bounds__(256) void k_conv1(const float* __restrict__ x,
                                               const float* __restrict__ w1,
                                               const float* __restrict__ b1) {
    extern __shared__ __align__(16) float smemA[];
    float* Wt = smemA;                 // [256][68] : Wt[c][m]
    float* Xs = smemA + C_*WT_PAD;     // [32][64]

    const int b  = blockIdx.y;
    const int p0 = blockIdx.x * 64;
    const int tid = threadIdx.x;

    // Load W1 transposed (one time). w1[m*256+c] -> Wt[c*68+m]
    for (int idx = tid; idx < COMP_*C_; idx += 256) {
        int m = idx >> 8, c = idx & 255;
        Wt[c*WT_PAD + m] = w1[idx];
    }

    const int tx = tid & 15;  // pixel group (4 pixels)
    const int ty = tid >> 4;  // m group (4 outputs)

    unsigned long long acc[4][2];
#pragma unroll
    for (int i = 0; i < 4; i++) { acc[i][0] = 0ull; acc[i][1] = 0ull; }

    const float* xb = x + (size_t)b*C_*HW_ + p0;

    for (int c0 = 0; c0 < C_; c0 += 32) {
        __syncthreads();
#pragma unroll
        for (int l = 0; l < 8; l++) {
            int idx = tid + l*256;
            int kk = idx >> 6, pp = idx & 63;
            Xs[kk*64 + pp] = xb[(size_t)(c0+kk)*HW_ + pp];
        }
        __syncthreads();
#pragma unroll
        for (int kk = 0; kk < 32; kk++) {
            const float4 wv = *(const float4*)&Wt[(c0+kk)*WT_PAD + ty*4];
            const ulonglong2 xv = *(const ulonglong2*)&Xs[kk*64 + tx*4];
            unsigned long long w0p = pack2(wv.x, wv.x);
            unsigned long long w1p = pack2(wv.y, wv.y);
            unsigned long long w2p = pack2(wv.z, wv.z);
            unsigned long long w3p = pack2(wv.w, wv.w);
            fma2(acc[0][0], w0p, xv.x); fma2(acc[0][1], w0p, xv.y);
            fma2(acc[1][0], w1p, xv.x); fma2(acc[1][1], w1p, xv.y);
            fma2(acc[2][0], w2p, xv.x); fma2(acc[2][1], w2p, xv.y);
            fma2(acc[3][0], w3p, xv.x); fma2(acc[3][1], w3p, xv.y);
        }
    }

#pragma unroll
    for (int i = 0; i < 4; i++) {
        int m = ty*4 + i;
        float bias = b1[m];
        float2 a0 = unpack2(acc[i][0]);
        float2 a1 = unpack2(acc[i][1]);
        float4 o = make_float4(a0.x + bias, a0.y + bias, a1.x + bias, a1.y + bias);
        *(float4*)&g_comp[((size_t)(b*COMP_ + m))*HW_ + p0 + tx*4] = o;
    }
}

// ---------------- Kernel B: 3x3 stride-2 conv (64 -> 25) raw logits ----------------
// grid (32, 4) : (ho-pair, batch). block 256. Dynamic smem: 64*5*130 + 25*64*9 floats = 224000 B.
#define CS_ROW   130
#define CS_CH    (5*CS_ROW)            // 650
#define B_SMEM_BYTES ((COMP_*CS_CH + KK_*COMP_*9) * 4)

__global__ __launch_bounds__(256) void k_conv2(const float* __restrict__ w2,
                                               const float* __restrict__ b2) {
    extern __shared__ __align__(16) float smemB[];
    float* cs  = smemB;                 // [64][5][130]
    float* w2s = smemB + COMP_*CS_CH;   // [25][64][9]

    const int b   = blockIdx.y;
    const int hop = blockIdx.x;         // output rows 2*hop, 2*hop+1
    const int tid = threadIdx.x;

    for (int idx = tid; idx < KK_*COMP_*9; idx += 256) w2s[idx] = w2[idx];

    const int r0 = 4*hop - 1;           // first input row for this pair
    for (int idx = tid; idx < COMP_*CS_CH; idx += 256) {
        int c   = idx / CS_CH;
        int rem = idx - c*CS_CH;
        int r   = rem / CS_ROW;
        int col = rem - r*CS_ROW;
        int gr = r0 + r, gc = col - 1;
        float v = 0.f;
        if ((unsigned)gr < (unsigned)H_ && (unsigned)gc < (unsigned)W_)
            v = g_comp[((size_t)(b*COMP_ + c)*H_ + gr)*W_ + gc];
        cs[idx] = v;
    }
    __syncthreads();

    const int wo = tid & 63;
    const int og = tid >> 6;                  // 0..3
    const int nO = (og == 0) ? 7 : 6;

    float acc0[7], acc1[7];
#pragma unroll
    for (int t = 0; t < 7; t++) { acc0[t] = 0.f; acc1[t] = 0.f; }

#pragma unroll 1
    for (int c = 0; c < COMP_; c++) {
        float xv[5][3];
        const float* csp = cs + c*CS_CH + 2*wo;
#pragma unroll
        for (int r = 0; r < 5; r++)
#pragma unroll
            for (int j = 0; j < 3; j++)
                xv[r][j] = csp[r*CS_ROW + j];

#pragma unroll
        for (int t = 0; t < 7; t++) {
            if (t < nO) {
                int o = og + 4*t;
                const float* wp = w2s + o*(COMP_*9) + c*9;
#pragma unroll
                for (int ki = 0; ki < 3; ki++)
#pragma unroll
                    for (int kj = 0; kj < 3; kj++) {
                        float w = wp[ki*3 + kj];
                        acc0[t] = fmaf(w, xv[ki][kj],   acc0[t]);
                        acc1[t] = fmaf(w, xv[ki+2][kj], acc1[t]);
                    }
            }
        }
    }

    const int ho0 = 2*hop;
#pragma unroll
    for (int t = 0; t < 7; t++) {
        if (t < nO) {
            int o = og + 4*t;
            float bias = b2[o];
            g_mask[(((size_t)b*KK_ + o)*HO_ + ho0    )*WO_ + wo] = acc0[t] + bias;
            g_mask[(((size_t)b*KK_ + o)*HO_ + ho0 + 1)*WO_ + wo] = acc1[t] + bias;
        }
    }
}

// ---------------- Kernel C: softmax(25) + CARAFE gather ----------------
// grid (64, 4, 4) : (ho, c-quarter, batch). block 256.
__global__ __launch_bounds__(256) void k_carafe(const float* __restrict__ x,
                                                float* __restrict__ out) {
    __shared__ float ms[KK_*64];

    const int ho = blockIdx.x;
    const int cq = blockIdx.y;
    const int b  = blockIdx.z;
    const int tid = threadIdx.x;

    for (int idx = tid; idx < KK_*64; idx += 256)
        ms[idx] = g_mask[(((size_t)b*KK_ + (idx >> 6))*HO_ + ho)*WO_ + (idx & 63)];
    __syncthreads();

    if (tid < 64) {
        float mx = -1e30f;
#pragma unroll
        for (int o = 0; o < KK_; o++) mx = fmaxf(mx, ms[o*64 + tid]);
        float e[KK_];
        float s = 0.f;
#pragma unroll
        for (int o = 0; o < KK_; o++) { e[o] = __expf(ms[o*64 + tid] - mx); s += e[o]; }
        float inv = 1.f / s;
#pragma unroll
        for (int o = 0; o < KK_; o++) ms[o*64 + tid] = e[o] * inv;
    }
    __syncthreads();

    const int wo  = tid & 63;
    const int cs4 = tid >> 6;

    float mw[KK_];
#pragma unroll
    for (int o = 0; o < KK_; o++) mw[o] = ms[o*64 + wo];

    const int r0 = 2*ho - 2;
    const int cb = 2*wo - 2;

#pragma unroll 1
    for (int t = 0; t < 16; t++) {
        int c = cq*64 + cs4 + 4*t;
        const float* xc = x + ((size_t)(b*C_ + c))*HW_;
        float acc = 0.f;
#pragma unroll
        for (int i = 0; i < 5; i++) {
            int r = r0 + i;
            if ((unsigned)r < (unsigned)H_) {
                const float* xr = xc + (size_t)r*W_;
#pragma unroll
                for (int j = 0; j < 5; j++) {
                    int col = cb + j;
                    if ((unsigned)col < (unsigned)W_)
                        acc = fmaf(mw[i*5 + j], __ldg(xr + col), acc);
                }
            }
        }
        out[(((size_t)b*C_ + c)*HO_ + ho)*WO_ + wo] = acc;
    }
}

// ---------------- launch ----------------
extern "C" void kernel_launch(void* const* d_in, const int* in_sizes, int n_in,
                              void* d_out, int out_size) {
    const float* x  = (const float*)d_in[0];
    const float* w1 = (const float*)d_in[1];
    const float* b1 = (const float*)d_in[2];
    const float* w2 = (const float*)d_in[3];
    const float* b2 = (const float*)d_in[4];
    float* out = (float*)d_out;

    cudaFuncSetAttribute(k_conv1, cudaFuncAttributeMaxDynamicSharedMemorySize, A_SMEM_BYTES);
    cudaFuncSetAttribute(k_conv2, cudaFuncAttributeMaxDynamicSharedMemorySize, B_SMEM_BYTES);

    k_conv1<<<dim3(256, 4), 256, A_SMEM_BYTES>>>(x, w1, b1);
    k_conv2<<<dim3(32, 4),  256, B_SMEM_BYTES>>>(w2, b2);
    k_carafe<<<dim3(64, 4, 4), 256>>>(x, out);
}

// round 3
// speedup vs baseline: 1.6022x; 1.6022x over previous
#include <cuda_runtime.h>
#include <cuda_bf16.h>
#include <cstdint>

#define B_    4
#define C_    256
#define H_    128
#define W_    128
#define HW_   (H_*W_)
#define COMP_ 64
#define KK_   25
#define HO_   64
#define WO_   64

// Scratch (device globals; allocation is forbidden)
// g_comp layout: [b][px (h*W+w)][ch]  (channel-minor!)
__device__ float g_comp[B_*HW_*COMP_];
__device__ float g_mask[B_*KK_*HO_*WO_];
__device__ __align__(16) unsigned char g_w1b[COMP_*C_*2];   // w1 bf16, plain [n][k]

__device__ __forceinline__ uint32_t smem_u32(const void* p) {
    uint32_t a;
    asm("{ .reg .u64 t; cvta.to.shared.u64 t, %1; cvt.u32.u64 %0, t; }" : "=r"(a) : "l"(p));
    return a;
}

// ================= Kernel P: w1 fp32 -> bf16 =================
__global__ void k_prep(const float* __restrict__ w1) {
    int idx = blockIdx.x * 256 + threadIdx.x;
    if (idx < COMP_ * C_)
        ((__nv_bfloat16*)g_w1b)[idx] = __float2bfloat16(w1[idx]);
}

// ================= Kernel A: 1x1 conv via mma.sync bf16 =================
// CTA: 256 thr (8 warps), 256 px. Warp: 32 px (two m16 tiles) x 64 out x K=256.
// smem: xs bf16 [64ch][256px] swizzled, ws bf16 [64n][256k] swizzled, bias[64].
#define XS_OFF   0
#define WS_OFF   32768
#define BIAS_OFF 65536
#define A_SMEM_BYTES (65536 + 256)

__global__ __launch_bounds__(256) void k_conv1(const float* __restrict__ x,
                                               const float* __restrict__ b1) {
    extern __shared__ __align__(16) char sm[];
    const uint32_t smb = smem_u32(sm);
    const int tid  = threadIdx.x;
    const int warp = tid >> 5;
    const int lane = tid & 31;
    const int b    = blockIdx.y;
    const int px0  = blockIdx.x * 256;

    // --- load w1 bf16 into swizzled smem [n][256k]: chunk cx ^= (n&7)
    {
        const uint32_t* wsrc = (const uint32_t*)g_w1b;
        for (int i = tid; i < COMP_ * C_ / 2; i += 256) {
            int n = i >> 7, u = i & 127;           // u = k/2
            int cx = u >> 2;                        // 16B chunk (8 bf16)
            uint32_t off = WS_OFF + n*512 + (uint32_t)((cx ^ (n & 7)) << 4) + (u & 3) * 4;
            *(uint32_t*)(sm + off) = wsrc[i];
        }
        if (tid < 64) ((float*)(sm + BIAS_OFF))[tid] = b1[tid];
    }

    float acc[2][8][4];
#pragma unroll
    for (int mt = 0; mt < 2; mt++)
#pragma unroll
        for (int nt = 0; nt < 8; nt++)
#pragma unroll
            for (int i = 0; i < 4; i++) acc[mt][nt][i] = 0.f;

    // ldmatrix lane geometry
    const int lj  = lane & 7;
    const int lg2 = (lane >> 3) & 1;
    const int lg4 = lane >> 4;
    const int g_  = lane >> 2;        // B/D fragment row group
    const int tig = lane & 3;

    const float* xbase = x + ((size_t)b * C_) * HW_ + px0;

    for (int chunk = 0; chunk < 4; chunk++) {
        __syncthreads();
        // --- load x chunk: 64 ch x 256 px fp32 -> bf16 swizzled smem
        const float4* xsrc = (const float4*)(xbase + (size_t)(chunk * 64) * HW_);
#pragma unroll
        for (int l = 0; l < 16; l++) {
            int id = l * 256 + tid;
            int ch = id >> 6, f4 = id & 63;
            float4 v = xsrc[(size_t)ch * (HW_/4) + f4];
            __nv_bfloat162 h0 = __float22bfloat162_rn(make_float2(v.x, v.y));
            __nv_bfloat162 h1 = __float22bfloat162_rn(make_float2(v.z, v.w));
            int cx = f4 >> 1;
            uint32_t off = XS_OFF + ch*512 + (uint32_t)((cx ^ (ch & 7)) << 4) + (f4 & 1) * 8;
            *(uint2*)(sm + off) = make_uint2(*(uint32_t*)&h0, *(uint32_t*)&h1);
        }
        __syncthreads();

#pragma unroll
        for (int s = 0; s < 4; s++) {
            // A fragments for two m16 tiles via ldmatrix.x4.trans
            uint32_t a[2][4];
            const int krow = s*16 + lj + lg4*8;
#pragma unroll
            for (int mt = 0; mt < 2; mt++) {
                int pxcol = warp*32 + mt*16 + lg2*8;
                uint32_t addr = smb + XS_OFF + krow*512
                              + (uint32_t)(((pxcol >> 3) ^ (krow & 7)) << 4);
                asm volatile("ldmatrix.sync.aligned.m8n8.x4.trans.shared.b16 "
                             "{%0,%1,%2,%3}, [%4];"
                             : "=r"(a[mt][0]), "=r"(a[mt][1]), "=r"(a[mt][2]), "=r"(a[mt][3])
                             : "r"(addr));
            }
            const int kabs = chunk*64 + s*16;
            const int cx0  = kabs >> 3;
#pragma unroll
            for (int nt = 0; nt < 8; nt++) {
                int n = nt*8 + g_;
                uint32_t ab0 = smb + WS_OFF + n*512
                             + (uint32_t)(((cx0     ) ^ (n & 7)) << 4) + tig*4;
                uint32_t ab1 = smb + WS_OFF + n*512
                             + (uint32_t)(((cx0 + 1) ^ (n & 7)) << 4) + tig*4;
                uint32_t b0, b1v;
                asm volatile("ld.shared.b32 %0, [%1];" : "=r"(b0)  : "r"(ab0));
                asm volatile("ld.shared.b32 %0, [%1];" : "=r"(b1v) : "r"(ab1));
#pragma unroll
                for (int mt = 0; mt < 2; mt++) {
                    asm volatile(
                        "mma.sync.aligned.m16n8k16.row.col.f32.bf16.bf16.f32 "
                        "{%0,%1,%2,%3}, {%4,%5,%6,%7}, {%8,%9}, {%0,%1,%2,%3};"
                        : "+f"(acc[mt][nt][0]), "+f"(acc[mt][nt][1]),
                          "+f"(acc[mt][nt][2]), "+f"(acc[mt][nt][3])
                        : "r"(a[mt][0]), "r"(a[mt][1]), "r"(a[mt][2]), "r"(a[mt][3]),
                          "r"(b0), "r"(b1v));
                }
            }
        }
    }

    // --- epilogue: D[g][tig*2..+1] -> g_comp[b][px][n] float2, coalesced 32B sectors
    const float* bias = (const float*)(sm + BIAS_OFF);
#pragma unroll
    for (int mt = 0; mt < 2; mt++) {
        int px_a = px0 + warp*32 + mt*16 + g_;
#pragma unroll
        for (int nt = 0; nt < 8; nt++) {
            int n = nt*8 + tig*2;
            float bx = bias[n], by = bias[n+1];
            float* p0 = g_comp + ((size_t)b*HW_ + px_a) * COMP_ + n;
            *(float2*)p0            = make_float2(acc[mt][nt][0] + bx, acc[mt][nt][1] + by);
            *(float2*)(p0 + 8*COMP_) = make_float2(acc[mt][nt][2] + bx, acc[mt][nt][3] + by);
        }
    }
}

// ================= Kernel B: 3x3 stride-2 conv (64 -> 25) =================
#define CS_ROW   130
#define CS_CH    (5*CS_ROW)
#define B_SMEM_BYTES ((COMP_*CS_CH + KK_*COMP_*9) * 4)

__global__ __launch_bounds__(256) void k_conv2(const float* __restrict__ w2,
                                               const float* __restrict__ b2) {
    extern __shared__ __align__(16) float smemB[];
    float* cs  = smemB;                 // [64][5][130]
    float* w2s = smemB + COMP_*CS_CH;   // [25][64][9]

    const int b   = blockIdx.y;
    const int hop = blockIdx.x;
    const int tid = threadIdx.x;

    for (int idx = tid; idx < KK_*COMP_*9; idx += 256) w2s[idx] = w2[idx];

    const int r0 = 4*hop - 1;
    // g_comp is channel-minor: read 64 contiguous floats per pixel (coalesced)
    for (int idx = tid; idx < COMP_*CS_CH; idx += 256) {
        int c   = idx & 63;
        int pix = idx >> 6;             // 0..649
        int r   = pix / CS_ROW;
        int col = pix - r*CS_ROW;
        int gr = r0 + r, gc = col - 1;
        float v = 0.f;
        if ((unsigned)gr < (unsigned)H_ && (unsigned)gc < (unsigned)W_)
            v = g_comp[((size_t)b*HW_ + gr*W_ + gc) * COMP_ + c];
        cs[c*CS_CH + r*CS_ROW + col] = v;
    }
    __syncthreads();

    const int wo = tid & 63;
    const int og = tid >> 6;
    const int nO = (og == 0) ? 7 : 6;

    float acc0[7], acc1[7];
#pragma unroll
    for (int t = 0; t < 7; t++) { acc0[t] = 0.f; acc1[t] = 0.f; }

#pragma unroll 1
    for (int c = 0; c < COMP_; c++) {
        float xv[5][3];
        const float* csp = cs + c*CS_CH + 2*wo;
#pragma unroll
        for (int r = 0; r < 5; r++)
#pragma unroll
            for (int j = 0; j < 3; j++)
                xv[r][j] = csp[r*CS_ROW + j];

#pragma unroll
        for (int t = 0; t < 7; t++) {
            if (t < nO) {
                int o = og + 4*t;
                const float* wp = w2s + o*(COMP_*9) + c*9;
#pragma unroll
                for (int ki = 0; ki < 3; ki++)
#pragma unroll
                    for (int kj = 0; kj < 3; kj++) {
                        float w = wp[ki*3 + kj];
                        acc0[t] = fmaf(w, xv[ki][kj],   acc0[t]);
                        acc1[t] = fmaf(w, xv[ki+2][kj], acc1[t]);
                    }
            }
        }
    }

    const int ho0 = 2*hop;
#pragma unroll
    for (int t = 0; t < 7; t++) {
        if (t < nO) {
            int o = og + 4*t;
            float bias = b2[o];
            g_mask[(((size_t)b*KK_ + o)*HO_ + ho0    )*WO_ + wo] = acc0[t] + bias;
            g_mask[(((size_t)b*KK_ + o)*HO_ + ho0 + 1)*WO_ + wo] = acc1[t] + bias;
        }
    }
}

// ================= Kernel C: softmax(25) + CARAFE gather (float2) =================
__global__ __launch_bounds__(256) void k_carafe(const float* __restrict__ x,
                                                float* __restrict__ out) {
    __shared__ float ms[KK_*64];

    const int ho = blockIdx.x;
    const int cq = blockIdx.y;
    const int b  = blockIdx.z;
    const int tid = threadIdx.x;

    for (int idx = tid; idx < KK_*64; idx += 256)
        ms[idx] = g_mask[(((size_t)b*KK_ + (idx >> 6))*HO_ + ho)*WO_ + (idx & 63)];
    __syncthreads();

    if (tid < 64) {
        float mx = -1e30f;
#pragma unroll
        for (int o = 0; o < KK_; o++) mx = fmaxf(mx, ms[o*64 + tid]);
        float e[KK_]; float s = 0.f;
#pragma unroll
        for (int o = 0; o < KK_; o++) { e[o] = __expf(ms[o*64 + tid] - mx); s += e[o]; }
        float inv = 1.f / s;
#pragma unroll
        for (int o = 0; o < KK_; o++) ms[o*64 + tid] = e[o] * inv;
    }
    __syncthreads();

    const int p    = tid & 31;   // output pair 2p, 2p+1
    const int slot = tid >> 5;

    float mw0[KK_], mw1[KK_];
#pragma unroll
    for (int o = 0; o < KK_; o++) { mw0[o] = ms[o*64 + 2*p]; mw1[o] = ms[o*64 + 2*p + 1]; }

    const int r0 = 2*ho - 2;
    const int cb = 4*p - 2;
    const bool okL = (p > 0);
    const bool okR = (p < 31);
    const float2 z2 = make_float2(0.f, 0.f);

#pragma unroll 1
    for (int t = 0; t < 8; t++) {
        const int c = cq*64 + slot*8 + t;
        const float* xc = x + ((size_t)(b*C_ + c)) * HW_;
        float a0 = 0.f, a1 = 0.f;
#pragma unroll
        for (int i = 0; i < 5; i++) {
            const int r = r0 + i;
            if ((unsigned)r < (unsigned)H_) {
                const float2* xr = (const float2*)(xc + (size_t)r*W_ + cb);
                float2 v0 = okL ? __ldg(xr + 0) : z2;
                float2 v1 = __ldg(xr + 1);
                float2 v2 = __ldg(xr + 2);
                float2 v3 = okR ? __ldg(xr + 3) : z2;
                a0 = fmaf(mw0[5*i+0], v0.x, a0);
                a0 = fmaf(mw0[5*i+1], v0.y, a0);
                a0 = fmaf(mw0[5*i+2], v1.x, a0);
                a0 = fmaf(mw0[5*i+3], v1.y, a0);
                a0 = fmaf(mw0[5*i+4], v2.x, a0);
                a1 = fmaf(mw1[5*i+0], v1.x, a1);
                a1 = fmaf(mw1[5*i+1], v1.y, a1);
                a1 = fmaf(mw1[5*i+2], v2.x, a1);
                a1 = fmaf(mw1[5*i+3], v2.y, a1);
                a1 = fmaf(mw1[5*i+4], v3.x, a1);
            }
        }
        *(float2*)&out[(((size_t)b*C_ + c)*HO_ + ho)*WO_ + 2*p] = make_float2(a0, a1);
    }
}

// ================= launch =================
extern "C" void kernel_launch(void* const* d_in, const int* in_sizes, int n_in,
                              void* d_out, int out_size) {
    const float* x  = (const float*)d_in[0];
    const float* w1 = (const float*)d_in[1];
    const float* b1 = (const float*)d_in[2];
    const float* w2 = (const float*)d_in[3];
    const float* b2 = (const float*)d_in[4];
    float* out = (float*)d_out;

    cudaFuncSetAttribute(k_conv1, cudaFuncAttributeMaxDynamicSharedMemorySize, A_SMEM_BYTES);
    cudaFuncSetAttribute(k_conv2, cudaFuncAttributeMaxDynamicSharedMemorySize, B_SMEM_BYTES);

    k_prep<<<64, 256>>>(w1);
    k_conv1<<<dim3(64, 4), 256, A_SMEM_BYTES>>>(x, b1);
    k_conv2<<<dim3(32, 4), 256, B_SMEM_BYTES>>>(w2, b2);
    k_carafe<<<dim3(64, 4, 4), 256>>>(x, out);
}